// round 2
// baseline (speedup 1.0000x reference)
#include <cuda_runtime.h>
#include <math.h>
#include <stdint.h>

// ---------------- Problem constants ----------------
#define BATCH   2
#define SEQ     2048
#define DMODEL  1024
#define DINNER  2048
#define DSTATE  16
#define DTRANK  64
#define DFFN    4096
#define MROWS   (BATCH*SEQ)      // 4096
#define DBCW    (DTRANK + 2*DSTATE) // 96

// ---------------- Scratch (static device globals; no allocation) ----------------
__device__ float g_xz [(size_t)MROWS * (2*DINNER)];  // 4096 x 4096  (xp | z)
__device__ float g_xp [(size_t)MROWS * DINNER];      // conv+silu output
__device__ float g_dbc[(size_t)MROWS * DBCW];        // 4096 x 96
__device__ float g_dt [(size_t)MROWS * DINNER];      // softplus(dt)
__device__ float g_yg [(size_t)MROWS * DINNER];      // gated scan output
__device__ float g_x2 [(size_t)MROWS * DMODEL];      // x + ssm_out
__device__ float g_hf [(size_t)MROWS * DFFN];        // gelu(ffn up)
__device__ float g_hstate[(size_t)BATCH * DINNER * DSTATE]; // fallback h_final

// ---------------- Generic NT GEMM: C[M,N] = A[M,K] * B[N,K]^T  (+epilogue) ----------------
// epi: 0=none, 1=softplus(acc+bias), 2=acc+res, 3=gelu(acc+bias), 4=acc+bias+res
#define BM 128
#define BN 128
#define BKT 16

__global__ __launch_bounds__(256)
void gemm_nt(int M, int N, int K,
             const float* __restrict__ A, int lda,
             const float* __restrict__ B, int ldb,
             float* __restrict__ C, int ldc,
             int epi,
             const float* __restrict__ bias,
             const float* __restrict__ res, int ldres)
{
    __shared__ float As[BKT][BM + 4];
    __shared__ float Bs[BKT][BN + 4];
    const int tid = threadIdx.x;
    const int bm = blockIdx.y * BM;
    const int bn = blockIdx.x * BN;
    const int tx = tid & 15;
    const int ty = tid >> 4;

    float acc[8][8];
#pragma unroll
    for (int i = 0; i < 8; i++)
#pragma unroll
        for (int j = 0; j < 8; j++) acc[i][j] = 0.f;

    const int lr = tid >> 2;        // 0..63
    const int lc = (tid & 3) * 4;   // 0,4,8,12

    for (int k0 = 0; k0 < K; k0 += BKT) {
#pragma unroll
        for (int i = 0; i < 2; i++) {
            int r = lr + i * 64;
            float4 va = make_float4(0.f, 0.f, 0.f, 0.f);
            int ga = bm + r;
            if (ga < M)
                va = *reinterpret_cast<const float4*>(A + (size_t)ga * lda + k0 + lc);
            As[lc + 0][r] = va.x; As[lc + 1][r] = va.y;
            As[lc + 2][r] = va.z; As[lc + 3][r] = va.w;
            float4 vb = make_float4(0.f, 0.f, 0.f, 0.f);
            int gb = bn + r;
            if (gb < N)
                vb = *reinterpret_cast<const float4*>(B + (size_t)gb * ldb + k0 + lc);
            Bs[lc + 0][r] = vb.x; Bs[lc + 1][r] = vb.y;
            Bs[lc + 2][r] = vb.z; Bs[lc + 3][r] = vb.w;
        }
        __syncthreads();
#pragma unroll
        for (int kk = 0; kk < BKT; kk++) {
            float a[8], b[8];
            *(float4*)&a[0] = *(const float4*)&As[kk][ty * 8];
            *(float4*)&a[4] = *(const float4*)&As[kk][ty * 8 + 4];
            *(float4*)&b[0] = *(const float4*)&Bs[kk][tx * 8];
            *(float4*)&b[4] = *(const float4*)&Bs[kk][tx * 8 + 4];
#pragma unroll
            for (int i = 0; i < 8; i++)
#pragma unroll
                for (int j = 0; j < 8; j++)
                    acc[i][j] = fmaf(a[i], b[j], acc[i][j]);
        }
        __syncthreads();
    }

#pragma unroll
    for (int i = 0; i < 8; i++) {
        int row = bm + ty * 8 + i;
        if (row >= M) continue;
#pragma unroll
        for (int j = 0; j < 8; j++) {
            int col = bn + tx * 8 + j;
            if (col >= N) continue;
            float v = acc[i][j];
            if (epi == 1) {                 // softplus(v + bias) (stable)
                v += bias[col];
                v = (v >= 0.f) ? (v + log1pf(expf(-v))) : log1pf(expf(v));
            } else if (epi == 2) {          // residual add
                v += res[(size_t)row * ldres + col];
            } else if (epi == 3) {          // exact gelu(v + bias)
                v += bias[col];
                v = 0.5f * v * (1.f + erff(v * 0.70710678118654752440f));
            } else if (epi == 4) {          // bias + residual
                v += bias[col] + res[(size_t)row * ldres + col];
            }
            C[(size_t)row * ldc + col] = v;
        }
    }
}

// ---------------- Depthwise causal conv (K=3) + bias + SiLU ----------------
__global__ __launch_bounds__(256)
void conv_silu_kernel(const float* __restrict__ xz,
                      const float* __restrict__ cw,
                      const float* __restrict__ cb,
                      float* __restrict__ xp)
{
    size_t idx = (size_t)blockIdx.x * blockDim.x + threadIdx.x;
    if (idx >= (size_t)MROWS * DINNER) return;
    int d = (int)(idx & (DINNER - 1));
    size_t bl = idx >> 11;               // b*SEQ + l
    int l = (int)(bl & (SEQ - 1));
    const float* p = xz + bl * (2 * DINNER) + d;   // xp part of xz
    float w0 = cw[d * 3 + 0], w1 = cw[d * 3 + 1], w2 = cw[d * 3 + 2];
    float acc = cb[d] + p[0] * w2;                 // in[l]   * w[2]
    if (l >= 1) acc += p[-(2 * DINNER)] * w1;      // in[l-1] * w[1]
    if (l >= 2) acc += p[-(ptrdiff_t)2 * (2 * DINNER)] * w0; // in[l-2] * w[0]
    float s = acc * (1.f / (1.f + __expf(-acc)));
    xp[idx] = s;
}

// ---------------- Selective scan: 16 lanes per (b,d) channel ----------------
// Fused: y = (scan_y + xp*Dp) * silu(z);  writes h_final.
__global__ __launch_bounds__(256)
void scan_kernel(const float* __restrict__ dt,
                 const float* __restrict__ dbc,
                 const float* __restrict__ xp,
                 const float* __restrict__ xz,
                 const float* __restrict__ A_log,
                 const float* __restrict__ Dp,
                 float* __restrict__ yg,
                 float* __restrict__ hfinal)
{
    int t = blockIdx.x * blockDim.x + threadIdx.x;
    int lane = t & (DSTATE - 1);
    int group = t >> 4;                  // (b, d)
    if (group >= BATCH * DINNER) return;
    int b = group >> 11;
    int d = group & (DINNER - 1);

    float a = -__expf(A_log[d * DSTATE + lane]);
    float Dv = Dp[d];
    float h = 0.f;

    const float* dt_p = dt  + (size_t)b * SEQ * DINNER + d;
    const float* x_p  = xp  + (size_t)b * SEQ * DINNER + d;
    const float* z_p  = xz  + (size_t)b * SEQ * (2 * DINNER) + DINNER + d;
    const float* bc_p = dbc + (size_t)b * SEQ * DBCW + DTRANK + lane;
    float*       y_p  = yg  + (size_t)b * SEQ * DINNER + d;

    for (int l = 0; l < SEQ; l++) {
        float dtv = dt_p[(size_t)l * DINNER];
        float xv  = x_p [(size_t)l * DINNER];
        float Bv  = bc_p[(size_t)l * DBCW];
        float Cv  = bc_p[(size_t)l * DBCW + DSTATE];
        h = __expf(dtv * a) * h + dtv * Bv * xv;
        float p = h * Cv;
        p += __shfl_xor_sync(0xffffffffu, p, 8);
        p += __shfl_xor_sync(0xffffffffu, p, 4);
        p += __shfl_xor_sync(0xffffffffu, p, 2);
        p += __shfl_xor_sync(0xffffffffu, p, 1);
        if (lane == 0) {
            float zv = z_p[(size_t)l * (2 * DINNER)];
            float sig = 1.f / (1.f + __expf(-zv));
            y_p[(size_t)l * DINNER] = (p + xv * Dv) * (zv * sig);
        }
    }
    hfinal[((size_t)b * DINNER + d) * DSTATE + lane] = h;
}

// ---------------- Launch ----------------
extern "C" void kernel_launch(void* const* d_in, const int* in_sizes, int n_in,
                              void* d_out, int out_size)
{
    const float* x        = (const float*)d_in[0];
    const float* in_w     = (const float*)d_in[1];
    const float* conv_w   = (const float*)d_in[2];
    const float* conv_b   = (const float*)d_in[3];
    const float* xproj_w  = (const float*)d_in[4];
    const float* dtproj_w = (const float*)d_in[5];
    const float* dtproj_b = (const float*)d_in[6];
    const float* A_log    = (const float*)d_in[7];
    const float* Dp       = (const float*)d_in[8];
    const float* out_w    = (const float*)d_in[9];
    const float* w1       = (const float*)d_in[10];
    const float* b1       = (const float*)d_in[11];
    const float* w2       = (const float*)d_in[12];
    const float* b2       = (const float*)d_in[13];
    float* out = (float*)d_out;

    float *xz, *xp, *dbc, *dt, *yg, *x2, *hf, *hstate;
    cudaGetSymbolAddress((void**)&xz,  g_xz);
    cudaGetSymbolAddress((void**)&xp,  g_xp);
    cudaGetSymbolAddress((void**)&dbc, g_dbc);
    cudaGetSymbolAddress((void**)&dt,  g_dt);
    cudaGetSymbolAddress((void**)&yg,  g_yg);
    cudaGetSymbolAddress((void**)&x2,  g_x2);
    cudaGetSymbolAddress((void**)&hf,  g_hf);
    cudaGetSymbolAddress((void**)&hstate, g_hstate);

    const int xout_elems = MROWS * DMODEL;             // 4,194,304
    const int h_elems    = BATCH * DINNER * DSTATE;    // 65,536
    float* hdst = (out_size >= xout_elems + h_elems) ? (out + xout_elems) : hstate;

    auto grid = [](int m, int n) { return dim3((unsigned)((n + BN - 1) / BN),
                                               (unsigned)((m + BM - 1) / BM)); };

    // G1: xz = x @ in_proj_w^T                      (4096 x 4096, K=1024)
    gemm_nt<<<grid(MROWS, 2 * DINNER), 256>>>(MROWS, 2 * DINNER, DMODEL,
        x, DMODEL, in_w, DMODEL, xz, 2 * DINNER, 0, nullptr, nullptr, 0);

    // conv (causal depthwise K=3) + bias + SiLU -> xp
    {
        size_t n = (size_t)MROWS * DINNER;
        conv_silu_kernel<<<(unsigned)((n + 255) / 256), 256>>>(xz, conv_w, conv_b, xp);
    }

    // G2: dbc = xp @ x_proj_w^T                     (4096 x 96, K=2048)
    gemm_nt<<<grid(MROWS, DBCW), 256>>>(MROWS, DBCW, DINNER,
        xp, DINNER, xproj_w, DINNER, dbc, DBCW, 0, nullptr, nullptr, 0);

    // G3: dt = softplus(dbc[:, :64] @ dt_proj_w^T + dt_proj_b)   (4096 x 2048, K=64)
    gemm_nt<<<grid(MROWS, DINNER), 256>>>(MROWS, DINNER, DTRANK,
        dbc, DBCW, dtproj_w, DTRANK, dt, DINNER, 1, dtproj_b, nullptr, 0);

    // SSM scan + D-skip + SiLU(z) gate -> yg, h_final
    scan_kernel<<<(BATCH * DINNER * DSTATE) / 256, 256>>>(dt, dbc, xp, xz, A_log, Dp, yg, hdst);

    // G4: x2 = x + yg @ out_proj_w^T                (4096 x 1024, K=2048)
    gemm_nt<<<grid(MROWS, DMODEL), 256>>>(MROWS, DMODEL, DINNER,
        yg, DINNER, out_w, DINNER, x2, DMODEL, 2, nullptr, x, DMODEL);

    // G5: hf = gelu(x2 @ w1^T + b1)                 (4096 x 4096, K=1024)
    gemm_nt<<<grid(MROWS, DFFN), 256>>>(MROWS, DFFN, DMODEL,
        x2, DMODEL, w1, DMODEL, hf, DFFN, 3, b1, nullptr, 0);

    // G6: out = x2 + hf @ w2^T + b2                 (4096 x 1024, K=4096)
    gemm_nt<<<grid(MROWS, DMODEL), 256>>>(MROWS, DMODEL, DFFN,
        hf, DFFN, w2, DFFN, out, DMODEL, 4, b2, x2, DMODEL);
}

// round 5
// speedup vs baseline: 1.4804x; 1.4804x over previous
#include <cuda_runtime.h>
#include <cuda_bf16.h>
#include <math.h>
#include <stdint.h>

// ---------------- Problem constants ----------------
#define BATCH   2
#define SEQ     2048
#define DMODEL  1024
#define DINNER  2048
#define DSTATE  16
#define DTRANK  64
#define DFFN    4096
#define MROWS   (BATCH*SEQ)          // 4096
#define DBCW    (DTRANK + 2*DSTATE)  // 96

typedef __nv_bfloat16 bf16;

// ---------------- Scratch (static device globals; no allocation) ----------------
__device__ float g_xz [(size_t)MROWS * (2*DINNER)];  // 4096 x 4096 (xp | z)
__device__ float g_xp [(size_t)MROWS * DINNER];
__device__ float g_dbc[(size_t)MROWS * DBCW];
__device__ float g_dt [(size_t)MROWS * DINNER];
__device__ float g_x2 [(size_t)MROWS * DMODEL];
__device__ float g_hstate[(size_t)BATCH * DINNER * DSTATE];

__device__ bf16 g_xh  [(size_t)MROWS * DMODEL],      g_xl  [(size_t)MROWS * DMODEL];
__device__ bf16 g_inwh[(size_t)(2*DINNER) * DMODEL], g_inwl[(size_t)(2*DINNER) * DMODEL];
__device__ bf16 g_xph [(size_t)MROWS * DINNER],      g_xpl [(size_t)MROWS * DINNER];
__device__ bf16 g_dbch[(size_t)MROWS * DBCW],        g_dbcl[(size_t)MROWS * DBCW];
__device__ bf16 g_dtwh[(size_t)DINNER * DTRANK],     g_dtwl[(size_t)DINNER * DTRANK];
__device__ bf16 g_xpwh[(size_t)DBCW * DINNER],       g_xpwl[(size_t)DBCW * DINNER];
__device__ bf16 g_owh [(size_t)DMODEL * DINNER],     g_owl [(size_t)DMODEL * DINNER];
__device__ bf16 g_w1h [(size_t)DFFN * DMODEL],       g_w1l [(size_t)DFFN * DMODEL];
__device__ bf16 g_w2h [(size_t)DMODEL * DFFN],       g_w2l [(size_t)DMODEL * DFFN];
__device__ bf16 g_ygh [(size_t)MROWS * DINNER],      g_ygl [(size_t)MROWS * DINNER];
__device__ bf16 g_x2h [(size_t)MROWS * DMODEL],      g_x2l [(size_t)MROWS * DMODEL];
__device__ bf16 g_hfh [(size_t)MROWS * DFFN],        g_hfl [(size_t)MROWS * DFFN];

// ---------------- low-level helpers (sm_80+ baseline; no 'a'-gated instrs) ----------------
__device__ __forceinline__ uint32_t smem_u32(const void* p) {
    uint32_t a;
    asm("{ .reg .u64 t; cvta.to.shared.u64 t, %1; cvt.u32.u64 %0, t; }" : "=r"(a) : "l"(p));
    return a;
}
__device__ __forceinline__ void cp_async16(uint32_t dst, const void* src, uint32_t srcBytes) {
    asm volatile("cp.async.cg.shared.global [%0], [%1], 16, %2;"
                 :: "r"(dst), "l"(src), "r"(srcBytes));
}
__device__ __forceinline__ void cp_commit() { asm volatile("cp.async.commit_group;"); }
__device__ __forceinline__ void cp_wait1()  { asm volatile("cp.async.wait_group 1;"); }

__device__ __forceinline__ void ldmatrix_x4(uint32_t* r, uint32_t addr) {
    asm volatile("ldmatrix.sync.aligned.m8n8.x4.shared.b16 {%0,%1,%2,%3}, [%4];"
                 : "=r"(r[0]), "=r"(r[1]), "=r"(r[2]), "=r"(r[3]) : "r"(addr));
}
__device__ __forceinline__ void ldmatrix_x2(uint32_t* r, uint32_t addr) {
    asm volatile("ldmatrix.sync.aligned.m8n8.x2.shared.b16 {%0,%1}, [%2];"
                 : "=r"(r[0]), "=r"(r[1]) : "r"(addr));
}
__device__ __forceinline__ void mma16816(float* d, const uint32_t* a, const uint32_t* b) {
    asm volatile("mma.sync.aligned.m16n8k16.row.col.f32.bf16.bf16.f32 "
                 "{%0,%1,%2,%3}, {%4,%5,%6,%7}, {%8,%9}, {%0,%1,%2,%3};"
                 : "+f"(d[0]), "+f"(d[1]), "+f"(d[2]), "+f"(d[3])
                 : "r"(a[0]), "r"(a[1]), "r"(a[2]), "r"(a[3]), "r"(b[0]), "r"(b[1]));
}

// ---------------- fp32 -> bf16 hi/lo split ----------------
__global__ __launch_bounds__(256)
void split_kernel(const float* __restrict__ in, bf16* __restrict__ hi, bf16* __restrict__ lo, int n)
{
    int i = blockIdx.x * blockDim.x + threadIdx.x;
    if (i >= n) return;
    float v = in[i];
    bf16 h = __float2bfloat16(v);
    hi[i] = h;
    lo[i] = __float2bfloat16(v - __bfloat162float(h));
}

// ---------------- split-bf16 mma.sync GEMM: C[M,N] = A[M,K] * B[N,K]^T ----------------
// epi: 0=plain fp32; 1=softplus(v+bias); 2=v+res; 3=gelu(v+bias); 4=v+bias+res
#define TCBM 128
#define TCBN 128
#define TCBK 32
#define ROWSTRIDE 40                    // bf16 elems per smem row (80 bytes)
#define TILE_B   (128 * ROWSTRIDE * 2)  // 10240 bytes per operand tile
#define STAGE_B  (4 * TILE_B)           // Ah, Al, Bh, Bl = 40960
#define GEMM_SMEM (2 * STAGE_B)         // 81920

__global__ __launch_bounds__(256, 1)
void gemm_tc(int M, int N, int K,
             const bf16* __restrict__ Ahi, const bf16* __restrict__ Alo, int lda,
             const bf16* __restrict__ Bhi, const bf16* __restrict__ Blo, int ldb,
             float* __restrict__ Cf, int ldc,
             bf16* __restrict__ Chi, bf16* __restrict__ Clo,
             int epi, const float* __restrict__ bias,
             const float* __restrict__ res, int ldres)
{
    extern __shared__ char smem[];
    const uint32_t sbase = smem_u32(smem);
    const int tid = threadIdx.x;
    const int wid = tid >> 5;
    const int lane = tid & 31;
    const int wm = (wid & 1) * 64;       // warp m offset in tile
    const int wn = (wid >> 1) * 32;      // warp n offset in tile

    const int bm = blockIdx.y * TCBM;
    const int bn = blockIdx.x * TCBN;
    const int nk = K / TCBK;

    float acc[4][4][4];
#pragma unroll
    for (int i = 0; i < 4; i++)
#pragma unroll
        for (int j = 0; j < 4; j++)
#pragma unroll
            for (int r = 0; r < 4; r++) acc[i][j][r] = 0.f;

    // ---- prefetch helper (stage s loads k chunk t) ----
    auto prefetch = [&](int t) {
        const int k0 = t * TCBK;
        const uint32_t stage = sbase + (uint32_t)(t & 1) * STAGE_B;
#pragma unroll
        for (int q = 0; q < 8; q++) {
            int idx = q * 256 + tid;     // 0..2047
            int mat = idx >> 9;          // 0:Ah 1:Al 2:Bh 3:Bl
            int r   = (idx >> 2) & 127;
            int ch  = idx & 3;
            const bf16* g; int grow, ld, lim;
            if (mat == 0)      { g = Ahi; grow = bm + r; ld = lda; lim = M; }
            else if (mat == 1) { g = Alo; grow = bm + r; ld = lda; lim = M; }
            else if (mat == 2) { g = Bhi; grow = bn + r; ld = ldb; lim = N; }
            else               { g = Blo; grow = bn + r; ld = ldb; lim = N; }
            uint32_t ok = (grow < lim) ? 16u : 0u;
            if (grow >= lim) grow = 0;   // keep address valid
            uint32_t dst = stage + (uint32_t)mat * TILE_B + (uint32_t)r * (ROWSTRIDE * 2) + (uint32_t)ch * 16;
            cp_async16(dst, g + (size_t)grow * ld + k0 + ch * 8, ok);
        }
    };

    prefetch(0);
    cp_commit();

    for (int t = 0; t < nk; t++) {
        if (t + 1 < nk) prefetch(t + 1);
        cp_commit();
        cp_wait1();
        __syncthreads();

        const uint32_t stage = sbase + (uint32_t)(t & 1) * STAGE_B;
        const uint32_t sAh = stage, sAl = stage + TILE_B, sBh = stage + 2 * TILE_B, sBl = stage + 3 * TILE_B;

#pragma unroll
        for (int kh = 0; kh < 2; kh++) {   // two k16 steps
            const uint32_t aoff = (uint32_t)(wm + ((lane & 15))) * (ROWSTRIDE * 2) + (uint32_t)(kh * 16 + (lane >> 4) * 8) * 2;
            const uint32_t boffbase = (uint32_t)(kh * 16 + ((lane >> 3) & 1) * 8) * 2;
            uint32_t ah[4][4], al[4][4], bh[4][2], bl[4][2];
#pragma unroll
            for (int mi = 0; mi < 4; mi++) {
                ldmatrix_x4(ah[mi], sAh + aoff + (uint32_t)(mi * 16) * (ROWSTRIDE * 2));
                ldmatrix_x4(al[mi], sAl + aoff + (uint32_t)(mi * 16) * (ROWSTRIDE * 2));
            }
#pragma unroll
            for (int ni = 0; ni < 4; ni++) {
                uint32_t boff = (uint32_t)(wn + ni * 8 + (lane & 7)) * (ROWSTRIDE * 2) + boffbase;
                ldmatrix_x2(bh[ni], sBh + boff);
                ldmatrix_x2(bl[ni], sBl + boff);
            }
#pragma unroll
            for (int mi = 0; mi < 4; mi++)
#pragma unroll
                for (int ni = 0; ni < 4; ni++) {
                    mma16816(acc[mi][ni], ah[mi], bh[ni]);
                    mma16816(acc[mi][ni], al[mi], bh[ni]);
                    mma16816(acc[mi][ni], ah[mi], bl[ni]);
                }
        }
        __syncthreads();
    }

    // ---- epilogue straight from registers ----
#pragma unroll
    for (int mi = 0; mi < 4; mi++) {
#pragma unroll
        for (int ni = 0; ni < 4; ni++) {
#pragma unroll
            for (int ri = 0; ri < 4; ri++) {
                int row = bm + wm + mi * 16 + (lane >> 2) + (ri >> 1) * 8;
                int col = bn + wn + ni * 8 + (lane & 3) * 2 + (ri & 1);
                if (row >= M || col >= N) continue;
                float v = acc[mi][ni][ri];
                if (epi == 1) {
                    v += bias[col];
                    v = (v >= 0.f) ? (v + log1pf(expf(-v))) : log1pf(expf(v));
                } else if (epi == 2) {
                    v += res[(size_t)row * ldres + col];
                } else if (epi == 3) {
                    v += bias[col];
                    v = 0.5f * v * (1.f + erff(v * 0.70710678118654752440f));
                } else if (epi == 4) {
                    v += bias[col] + res[(size_t)row * ldres + col];
                }
                if (Cf) Cf[(size_t)row * ldc + col] = v;
                if (Chi) {
                    bf16 h = __float2bfloat16(v);
                    Chi[(size_t)row * ldc + col] = h;
                    Clo[(size_t)row * ldc + col] = __float2bfloat16(v - __bfloat162float(h));
                }
            }
        }
    }
}

// ---------------- Depthwise causal conv (K=3) + bias + SiLU (+ bf16 split out) ----------------
__global__ __launch_bounds__(256)
void conv_silu_kernel(const float* __restrict__ xz,
                      const float* __restrict__ cw,
                      const float* __restrict__ cb,
                      float* __restrict__ xp,
                      bf16* __restrict__ xph, bf16* __restrict__ xpl)
{
    size_t idx = (size_t)blockIdx.x * blockDim.x + threadIdx.x;
    if (idx >= (size_t)MROWS * DINNER) return;
    int d = (int)(idx & (DINNER - 1));
    size_t bl = idx >> 11;
    int l = (int)(bl & (SEQ - 1));
    const float* p = xz + bl * (2 * DINNER) + d;
    float w0 = cw[d * 3 + 0], w1 = cw[d * 3 + 1], w2 = cw[d * 3 + 2];
    float acc = cb[d] + p[0] * w2;
    if (l >= 1) acc += p[-(2 * DINNER)] * w1;
    if (l >= 2) acc += p[-(ptrdiff_t)2 * (2 * DINNER)] * w0;
    float s = acc * (1.f / (1.f + __expf(-acc)));
    xp[idx] = s;
    bf16 h = __float2bfloat16(s);
    xph[idx] = h;
    xpl[idx] = __float2bfloat16(s - __bfloat162float(h));
}

// ---------------- Selective scan: 16 lanes per (b,d); gated output as bf16 hi/lo ----------------
__global__ __launch_bounds__(256)
void scan_kernel(const float* __restrict__ dt,
                 const float* __restrict__ dbc,
                 const float* __restrict__ xp,
                 const float* __restrict__ xz,
                 const float* __restrict__ A_log,
                 const float* __restrict__ Dp,
                 bf16* __restrict__ ygh, bf16* __restrict__ ygl,
                 float* __restrict__ hfinal)
{
    int t = blockIdx.x * blockDim.x + threadIdx.x;
    int lane = t & (DSTATE - 1);
    int group = t >> 4;
    if (group >= BATCH * DINNER) return;
    int b = group >> 11;
    int d = group & (DINNER - 1);

    float a = -__expf(A_log[d * DSTATE + lane]);
    float Dv = Dp[d];
    float h = 0.f;

    const float* dt_p = dt  + (size_t)b * SEQ * DINNER + d;
    const float* x_p  = xp  + (size_t)b * SEQ * DINNER + d;
    const float* z_p  = xz  + (size_t)b * SEQ * (2 * DINNER) + DINNER + d;
    const float* bc_p = dbc + (size_t)b * SEQ * DBCW + DTRANK + lane;
    size_t ybase = (size_t)b * SEQ * DINNER + d;

    for (int l = 0; l < SEQ; l++) {
        float dtv = dt_p[(size_t)l * DINNER];
        float xv  = x_p [(size_t)l * DINNER];
        float Bv  = bc_p[(size_t)l * DBCW];
        float Cv  = bc_p[(size_t)l * DBCW + DSTATE];
        h = __expf(dtv * a) * h + dtv * Bv * xv;
        float p = h * Cv;
        p += __shfl_xor_sync(0xffffffffu, p, 8);
        p += __shfl_xor_sync(0xffffffffu, p, 4);
        p += __shfl_xor_sync(0xffffffffu, p, 2);
        p += __shfl_xor_sync(0xffffffffu, p, 1);
        if (lane == 0) {
            float zv = z_p[(size_t)l * (2 * DINNER)];
            float sig = 1.f / (1.f + __expf(-zv));
            float yv = (p + xv * Dv) * (zv * sig);
            bf16 hb = __float2bfloat16(yv);
            ygh[ybase + (size_t)l * DINNER] = hb;
            ygl[ybase + (size_t)l * DINNER] = __float2bfloat16(yv - __bfloat162float(hb));
        }
    }
    hfinal[((size_t)b * DINNER + d) * DSTATE + lane] = h;
}

// ---------------- Launch ----------------
extern "C" void kernel_launch(void* const* d_in, const int* in_sizes, int n_in,
                              void* d_out, int out_size)
{
    const float* x        = (const float*)d_in[0];
    const float* in_w     = (const float*)d_in[1];
    const float* conv_w   = (const float*)d_in[2];
    const float* conv_b   = (const float*)d_in[3];
    const float* xproj_w  = (const float*)d_in[4];
    const float* dtproj_w = (const float*)d_in[5];
    const float* dtproj_b = (const float*)d_in[6];
    const float* A_log    = (const float*)d_in[7];
    const float* Dp       = (const float*)d_in[8];
    const float* out_w    = (const float*)d_in[9];
    const float* w1       = (const float*)d_in[10];
    const float* b1       = (const float*)d_in[11];
    const float* w2       = (const float*)d_in[12];
    const float* b2       = (const float*)d_in[13];
    float* out = (float*)d_out;

    float *xz, *xp, *dbc, *dt, *x2, *hstate;
    bf16 *xh, *xl, *inwh, *inwl, *xph, *xpl, *dbch, *dbcl, *dtwh, *dtwl, *xpwh, *xpwl;
    bf16 *owh, *owl, *w1h, *w1l, *w2h, *w2l, *ygh, *ygl, *x2h, *x2l, *hfh, *hfl;
    cudaGetSymbolAddress((void**)&xz,  g_xz);
    cudaGetSymbolAddress((void**)&xp,  g_xp);
    cudaGetSymbolAddress((void**)&dbc, g_dbc);
    cudaGetSymbolAddress((void**)&dt,  g_dt);
    cudaGetSymbolAddress((void**)&x2,  g_x2);
    cudaGetSymbolAddress((void**)&hstate, g_hstate);
    cudaGetSymbolAddress((void**)&xh,  g_xh);   cudaGetSymbolAddress((void**)&xl,  g_xl);
    cudaGetSymbolAddress((void**)&inwh,g_inwh); cudaGetSymbolAddress((void**)&inwl,g_inwl);
    cudaGetSymbolAddress((void**)&xph, g_xph);  cudaGetSymbolAddress((void**)&xpl, g_xpl);
    cudaGetSymbolAddress((void**)&dbch,g_dbch); cudaGetSymbolAddress((void**)&dbcl,g_dbcl);
    cudaGetSymbolAddress((void**)&dtwh,g_dtwh); cudaGetSymbolAddress((void**)&dtwl,g_dtwl);
    cudaGetSymbolAddress((void**)&xpwh,g_xpwh); cudaGetSymbolAddress((void**)&xpwl,g_xpwl);
    cudaGetSymbolAddress((void**)&owh, g_owh);  cudaGetSymbolAddress((void**)&owl, g_owl);
    cudaGetSymbolAddress((void**)&w1h, g_w1h);  cudaGetSymbolAddress((void**)&w1l, g_w1l);
    cudaGetSymbolAddress((void**)&w2h, g_w2h);  cudaGetSymbolAddress((void**)&w2l, g_w2l);
    cudaGetSymbolAddress((void**)&ygh, g_ygh);  cudaGetSymbolAddress((void**)&ygl, g_ygl);
    cudaGetSymbolAddress((void**)&x2h, g_x2h);  cudaGetSymbolAddress((void**)&x2l, g_x2l);
    cudaGetSymbolAddress((void**)&hfh, g_hfh);  cudaGetSymbolAddress((void**)&hfl, g_hfl);

    cudaFuncSetAttribute(gemm_tc, cudaFuncAttributeMaxDynamicSharedMemorySize, GEMM_SMEM);

    const int xout_elems = MROWS * DMODEL;
    const int h_elems    = BATCH * DINNER * DSTATE;
    float* hdst = (out_size >= xout_elems + h_elems) ? (out + xout_elems) : hstate;

    auto grid = [](int m, int n) { return dim3((unsigned)((n + TCBN - 1) / TCBN),
                                               (unsigned)((m + TCBM - 1) / TCBM)); };
    auto sgrid = [](int n) { return (unsigned)((n + 255) / 256); };

    // Weight / input splits (fp32 -> bf16 hi/lo)
    split_kernel<<<sgrid(MROWS * DMODEL), 256>>>(x, xh, xl, MROWS * DMODEL);
    split_kernel<<<sgrid(2 * DINNER * DMODEL), 256>>>(in_w, inwh, inwl, 2 * DINNER * DMODEL);
    split_kernel<<<sgrid(DBCW * DINNER), 256>>>(xproj_w, xpwh, xpwl, DBCW * DINNER);
    split_kernel<<<sgrid(DINNER * DTRANK), 256>>>(dtproj_w, dtwh, dtwl, DINNER * DTRANK);
    split_kernel<<<sgrid(DMODEL * DINNER), 256>>>(out_w, owh, owl, DMODEL * DINNER);
    split_kernel<<<sgrid(DFFN * DMODEL), 256>>>(w1, w1h, w1l, DFFN * DMODEL);
    split_kernel<<<sgrid(DMODEL * DFFN), 256>>>(w2, w2h, w2l, DMODEL * DFFN);

    // G1: xz = x @ in_proj_w^T   (4096 x 4096, K=1024)
    gemm_tc<<<grid(MROWS, 2 * DINNER), 256, GEMM_SMEM>>>(MROWS, 2 * DINNER, DMODEL,
        xh, xl, DMODEL, inwh, inwl, DMODEL, xz, 2 * DINNER, nullptr, nullptr, 0, nullptr, nullptr, 0);

    // conv + SiLU -> xp (fp32 + hi/lo)
    conv_silu_kernel<<<sgrid(MROWS * DINNER), 256>>>(xz, conv_w, conv_b, xp, xph, xpl);

    // G2: dbc = xp @ x_proj_w^T  (4096 x 96, K=2048)
    gemm_tc<<<grid(MROWS, DBCW), 256, GEMM_SMEM>>>(MROWS, DBCW, DINNER,
        xph, xpl, DINNER, xpwh, xpwl, DINNER, dbc, DBCW, nullptr, nullptr, 0, nullptr, nullptr, 0);

    // split dbc for G3 (small)
    split_kernel<<<sgrid(MROWS * DBCW), 256>>>(dbc, dbch, dbcl, MROWS * DBCW);

    // G3: dt = softplus(dbc[:, :64] @ dt_proj_w^T + b)  (4096 x 2048, K=64)
    gemm_tc<<<grid(MROWS, DINNER), 256, GEMM_SMEM>>>(MROWS, DINNER, DTRANK,
        dbch, dbcl, DBCW, dtwh, dtwl, DTRANK, dt, DINNER, nullptr, nullptr, 1, dtproj_b, nullptr, 0);

    // SSM scan + D-skip + SiLU(z) gate -> yg (hi/lo), h_final
    scan_kernel<<<(BATCH * DINNER * DSTATE) / 256, 256>>>(dt, dbc, xp, xz, A_log, Dp, ygh, ygl, hdst);

    // G4: x2 = x + yg @ out_proj_w^T   (4096 x 1024, K=2048)  (fp32 + hi/lo)
    gemm_tc<<<grid(MROWS, DMODEL), 256, GEMM_SMEM>>>(MROWS, DMODEL, DINNER,
        ygh, ygl, DINNER, owh, owl, DINNER, x2, DMODEL, x2h, x2l, 2, nullptr, x, DMODEL);

    // G5: hf = gelu(x2 @ w1^T + b1)    (4096 x 4096, K=1024)  (hi/lo only)
    gemm_tc<<<grid(MROWS, DFFN), 256, GEMM_SMEM>>>(MROWS, DFFN, DMODEL,
        x2h, x2l, DMODEL, w1h, w1l, DMODEL, nullptr, DFFN, hfh, hfl, 3, b1, nullptr, 0);

    // G6: out = x2 + hf @ w2^T + b2    (4096 x 1024, K=4096)
    gemm_tc<<<grid(MROWS, DMODEL), 256, GEMM_SMEM>>>(MROWS, DMODEL, DFFN,
        hfh, hfl, DFFN, w2h, w2l, DFFN, out, DMODEL, nullptr, nullptr, 4, b2, x2, DMODEL);
}

// round 6
// speedup vs baseline: 1.5751x; 1.0640x over previous
#include <cuda_runtime.h>
#include <cuda_bf16.h>
#include <math.h>
#include <stdint.h>

// ---------------- Problem constants ----------------
#define BATCH   2
#define SEQ     2048
#define DMODEL  1024
#define DINNER  2048
#define DSTATE  16
#define DTRANK  64
#define DFFN    4096
#define MROWS   (BATCH*SEQ)          // 4096
#define DBCW    (DTRANK + 2*DSTATE)  // 96

typedef __nv_bfloat16 bf16;

// ---------------- Scratch (static device globals; no allocation) ----------------
__device__ float g_xz [(size_t)MROWS * (2*DINNER)];  // 4096 x 4096 (xp | z)
__device__ float g_xp [(size_t)MROWS * DINNER];
__device__ float g_dbc[(size_t)MROWS * DBCW];
__device__ float g_dt [(size_t)MROWS * DINNER];
__device__ float g_x2 [(size_t)MROWS * DMODEL];
__device__ float g_hstate[(size_t)BATCH * DINNER * DSTATE];

__device__ bf16 g_xh  [(size_t)MROWS * DMODEL],      g_xl  [(size_t)MROWS * DMODEL];
__device__ bf16 g_inwh[(size_t)(2*DINNER) * DMODEL], g_inwl[(size_t)(2*DINNER) * DMODEL];
__device__ bf16 g_xph [(size_t)MROWS * DINNER],      g_xpl [(size_t)MROWS * DINNER];
__device__ bf16 g_dbch[(size_t)MROWS * DBCW],        g_dbcl[(size_t)MROWS * DBCW];
__device__ bf16 g_dtwh[(size_t)DINNER * DTRANK],     g_dtwl[(size_t)DINNER * DTRANK];
__device__ bf16 g_xpwh[(size_t)DBCW * DINNER],       g_xpwl[(size_t)DBCW * DINNER];
__device__ bf16 g_owh [(size_t)DMODEL * DINNER],     g_owl [(size_t)DMODEL * DINNER];
__device__ bf16 g_w1h [(size_t)DFFN * DMODEL],       g_w1l [(size_t)DFFN * DMODEL];
__device__ bf16 g_w2h [(size_t)DMODEL * DFFN],       g_w2l [(size_t)DMODEL * DFFN];
__device__ bf16 g_ygh [(size_t)MROWS * DINNER],      g_ygl [(size_t)MROWS * DINNER];
__device__ bf16 g_x2h [(size_t)MROWS * DMODEL],      g_x2l [(size_t)MROWS * DMODEL];
__device__ bf16 g_hfh [(size_t)MROWS * DFFN],        g_hfl [(size_t)MROWS * DFFN];

// ---------------- low-level helpers (sm_80+ baseline; no 'a'-gated instrs) ----------------
__device__ __forceinline__ uint32_t smem_u32(const void* p) {
    uint32_t a;
    asm("{ .reg .u64 t; cvta.to.shared.u64 t, %1; cvt.u32.u64 %0, t; }" : "=r"(a) : "l"(p));
    return a;
}
__device__ __forceinline__ void cp_async16(uint32_t dst, const void* src, uint32_t srcBytes) {
    asm volatile("cp.async.cg.shared.global [%0], [%1], 16, %2;"
                 :: "r"(dst), "l"(src), "r"(srcBytes));
}
__device__ __forceinline__ void cp_commit() { asm volatile("cp.async.commit_group;"); }
__device__ __forceinline__ void cp_wait1()  { asm volatile("cp.async.wait_group 1;"); }

__device__ __forceinline__ void ldmatrix_x4(uint32_t* r, uint32_t addr) {
    asm volatile("ldmatrix.sync.aligned.m8n8.x4.shared.b16 {%0,%1,%2,%3}, [%4];"
                 : "=r"(r[0]), "=r"(r[1]), "=r"(r[2]), "=r"(r[3]) : "r"(addr));
}
__device__ __forceinline__ void ldmatrix_x2(uint32_t* r, uint32_t addr) {
    asm volatile("ldmatrix.sync.aligned.m8n8.x2.shared.b16 {%0,%1}, [%2];"
                 : "=r"(r[0]), "=r"(r[1]) : "r"(addr));
}
__device__ __forceinline__ void mma16816(float* d, const uint32_t* a, const uint32_t* b) {
    asm volatile("mma.sync.aligned.m16n8k16.row.col.f32.bf16.bf16.f32 "
                 "{%0,%1,%2,%3}, {%4,%5,%6,%7}, {%8,%9}, {%0,%1,%2,%3};"
                 : "+f"(d[0]), "+f"(d[1]), "+f"(d[2]), "+f"(d[3])
                 : "r"(a[0]), "r"(a[1]), "r"(a[2]), "r"(a[3]), "r"(b[0]), "r"(b[1]));
}

// ---------------- fused fp32 -> bf16 hi/lo split over all weight/input tensors ----------------
// All sizes in float4 units; boundaries precomputed.
#define F4_X    1048576u                  // x           4096x1024
#define F4_INW  1048576u                  // in_proj_w   4096x1024
#define F4_XPW    49152u                  // x_proj_w      96x2048
#define F4_DTW    32768u                  // dt_proj_w   2048x64
#define F4_OW    524288u                  // out_proj_w  1024x2048
#define F4_W1   1048576u                  // w1          4096x1024
#define F4_W2   1048576u                  // w2          1024x4096
#define F4_B0   F4_X
#define F4_B1   (F4_B0 + F4_INW)
#define F4_B2   (F4_B1 + F4_XPW)
#define F4_B3   (F4_B2 + F4_DTW)
#define F4_B4   (F4_B3 + F4_OW)
#define F4_B5   (F4_B4 + F4_W1)
#define F4_B6   (F4_B5 + F4_W2)           // 4800512

struct BF4 { bf16 v[4]; };

__global__ __launch_bounds__(256)
void split_all(const float* __restrict__ x,    bf16* __restrict__ xh,   bf16* __restrict__ xl,
               const float* __restrict__ inw,  bf16* __restrict__ inwh, bf16* __restrict__ inwl,
               const float* __restrict__ xpw,  bf16* __restrict__ xpwh, bf16* __restrict__ xpwl,
               const float* __restrict__ dtw,  bf16* __restrict__ dtwh, bf16* __restrict__ dtwl,
               const float* __restrict__ ow,   bf16* __restrict__ owh,  bf16* __restrict__ owl,
               const float* __restrict__ w1,   bf16* __restrict__ w1h,  bf16* __restrict__ w1l,
               const float* __restrict__ w2,   bf16* __restrict__ w2h,  bf16* __restrict__ w2l)
{
    uint32_t i = blockIdx.x * blockDim.x + threadIdx.x;
    if (i >= F4_B6) return;
    const float* src; bf16 *hi, *lo; uint32_t off;
    if      (i < F4_B0) { src = x;   hi = xh;   lo = xl;   off = i; }
    else if (i < F4_B1) { src = inw; hi = inwh; lo = inwl; off = i - F4_B0; }
    else if (i < F4_B2) { src = xpw; hi = xpwh; lo = xpwl; off = i - F4_B1; }
    else if (i < F4_B3) { src = dtw; hi = dtwh; lo = dtwl; off = i - F4_B2; }
    else if (i < F4_B4) { src = ow;  hi = owh;  lo = owl;  off = i - F4_B3; }
    else if (i < F4_B5) { src = w1;  hi = w1h;  lo = w1l;  off = i - F4_B4; }
    else                { src = w2;  hi = w2h;  lo = w2l;  off = i - F4_B5; }
    float4 v = reinterpret_cast<const float4*>(src)[off];
    BF4 h, l;
    float a[4] = {v.x, v.y, v.z, v.w};
#pragma unroll
    for (int k = 0; k < 4; k++) {
        bf16 hb = __float2bfloat16(a[k]);
        h.v[k] = hb;
        l.v[k] = __float2bfloat16(a[k] - __bfloat162float(hb));
    }
    reinterpret_cast<BF4*>(hi)[off] = h;
    reinterpret_cast<BF4*>(lo)[off] = l;
}

// ---------------- split-bf16 mma.sync GEMM: C[M,N] = A[M,K] * B[N,K]^T ----------------
// 3-stage cp.async pipeline, one __syncthreads per K-iter.
// epi: 0=plain fp32; 1=softplus(v+bias); 2=v+res; 3=gelu(v+bias); 4=v+bias+res
#define TCBM 128
#define TCBN 128
#define TCBK 32
#define ROWSTRIDE 40                    // bf16 elems per smem row (80 bytes)
#define TILE_B   (128 * ROWSTRIDE * 2)  // 10240 bytes per operand tile
#define STAGE_B  (4 * TILE_B)           // Ah, Al, Bh, Bl = 40960
#define NSTAGE   3
#define GEMM_SMEM (NSTAGE * STAGE_B)    // 122880

__global__ __launch_bounds__(256, 1)
void gemm_tc(int M, int N, int K,
             const bf16* __restrict__ Ahi, const bf16* __restrict__ Alo, int lda,
             const bf16* __restrict__ Bhi, const bf16* __restrict__ Blo, int ldb,
             float* __restrict__ Cf, int ldc,
             bf16* __restrict__ Chi, bf16* __restrict__ Clo,
             int epi, const float* __restrict__ bias,
             const float* __restrict__ res, int ldres)
{
    extern __shared__ char smem[];
    const uint32_t sbase = smem_u32(smem);
    const int tid = threadIdx.x;
    const int wid = tid >> 5;
    const int lane = tid & 31;
    const int wm = (wid & 1) * 64;       // warp m offset in tile
    const int wn = (wid >> 1) * 32;      // warp n offset in tile

    const int bm = blockIdx.y * TCBM;
    const int bn = blockIdx.x * TCBN;
    const int nk = K / TCBK;

    float acc[4][4][4];
#pragma unroll
    for (int i = 0; i < 4; i++)
#pragma unroll
        for (int j = 0; j < 4; j++)
#pragma unroll
            for (int r = 0; r < 4; r++) acc[i][j][r] = 0.f;

    auto prefetch = [&](int t, int stg) {
        const int k0 = t * TCBK;
        const uint32_t stage = sbase + (uint32_t)stg * STAGE_B;
#pragma unroll
        for (int q = 0; q < 8; q++) {
            int idx = q * 256 + tid;     // 0..2047
            int mat = idx >> 9;          // 0:Ah 1:Al 2:Bh 3:Bl
            int r   = (idx >> 2) & 127;
            int ch  = idx & 3;
            const bf16* g; int grow, ld, lim;
            if (mat == 0)      { g = Ahi; grow = bm + r; ld = lda; lim = M; }
            else if (mat == 1) { g = Alo; grow = bm + r; ld = lda; lim = M; }
            else if (mat == 2) { g = Bhi; grow = bn + r; ld = ldb; lim = N; }
            else               { g = Blo; grow = bn + r; ld = ldb; lim = N; }
            uint32_t ok = (grow < lim) ? 16u : 0u;
            if (grow >= lim) grow = 0;   // keep address valid
            uint32_t dst = stage + (uint32_t)mat * TILE_B + (uint32_t)r * (ROWSTRIDE * 2) + (uint32_t)ch * 16;
            cp_async16(dst, g + (size_t)grow * ld + k0 + ch * 8, ok);
        }
    };

    prefetch(0, 0);
    cp_commit();
    if (nk > 1) prefetch(1, 1);
    cp_commit();

    int cstg = 0, pstg = 2;
    for (int t = 0; t < nk; t++) {
        cp_wait1();                         // stage t resident
        __syncthreads();                    // all warps done with stage pstg's last use
        if (t + 2 < nk) prefetch(t + 2, pstg);
        cp_commit();

        const uint32_t stage = sbase + (uint32_t)cstg * STAGE_B;
        const uint32_t sAh = stage, sAl = stage + TILE_B, sBh = stage + 2 * TILE_B, sBl = stage + 3 * TILE_B;

#pragma unroll
        for (int kh = 0; kh < 2; kh++) {   // two k16 steps
            const uint32_t aoff = (uint32_t)(wm + ((lane & 15))) * (ROWSTRIDE * 2) + (uint32_t)(kh * 16 + (lane >> 4) * 8) * 2;
            const uint32_t boffbase = (uint32_t)(kh * 16 + ((lane >> 3) & 1) * 8) * 2;
            uint32_t ah[4][4], al[4][4], bh[4][2], bl[4][2];
#pragma unroll
            for (int mi = 0; mi < 4; mi++) {
                ldmatrix_x4(ah[mi], sAh + aoff + (uint32_t)(mi * 16) * (ROWSTRIDE * 2));
                ldmatrix_x4(al[mi], sAl + aoff + (uint32_t)(mi * 16) * (ROWSTRIDE * 2));
            }
#pragma unroll
            for (int ni = 0; ni < 4; ni++) {
                uint32_t boff = (uint32_t)(wn + ni * 8 + (lane & 7)) * (ROWSTRIDE * 2) + boffbase;
                ldmatrix_x2(bh[ni], sBh + boff);
                ldmatrix_x2(bl[ni], sBl + boff);
            }
#pragma unroll
            for (int mi = 0; mi < 4; mi++)
#pragma unroll
                for (int ni = 0; ni < 4; ni++) {
                    mma16816(acc[mi][ni], ah[mi], bh[ni]);
                    mma16816(acc[mi][ni], al[mi], bh[ni]);
                    mma16816(acc[mi][ni], ah[mi], bl[ni]);
                }
        }
        if (++cstg == NSTAGE) cstg = 0;
        if (++pstg == NSTAGE) pstg = 0;
    }

    // ---- epilogue straight from registers ----
#pragma unroll
    for (int mi = 0; mi < 4; mi++) {
#pragma unroll
        for (int ni = 0; ni < 4; ni++) {
#pragma unroll
            for (int ri = 0; ri < 4; ri++) {
                int row = bm + wm + mi * 16 + (lane >> 2) + (ri >> 1) * 8;
                int col = bn + wn + ni * 8 + (lane & 3) * 2 + (ri & 1);
                if (row >= M || col >= N) continue;
                float v = acc[mi][ni][ri];
                if (epi == 1) {
                    v += bias[col];
                    v = (v >= 0.f) ? (v + log1pf(expf(-v))) : log1pf(expf(v));
                } else if (epi == 2) {
                    v += res[(size_t)row * ldres + col];
                } else if (epi == 3) {
                    v += bias[col];
                    v = 0.5f * v * (1.f + erff(v * 0.70710678118654752440f));
                } else if (epi == 4) {
                    v += bias[col] + res[(size_t)row * ldres + col];
                }
                if (Cf) Cf[(size_t)row * ldc + col] = v;
                if (Chi) {
                    bf16 h = __float2bfloat16(v);
                    Chi[(size_t)row * ldc + col] = h;
                    Clo[(size_t)row * ldc + col] = __float2bfloat16(v - __bfloat162float(h));
                }
            }
        }
    }
}

// ---------------- Depthwise causal conv (K=3) + bias + SiLU (+ bf16 split out) ----------------
__global__ __launch_bounds__(256)
void conv_silu_kernel(const float* __restrict__ xz,
                      const float* __restrict__ cw,
                      const float* __restrict__ cb,
                      float* __restrict__ xp,
                      bf16* __restrict__ xph, bf16* __restrict__ xpl)
{
    size_t idx = (size_t)blockIdx.x * blockDim.x + threadIdx.x;
    if (idx >= (size_t)MROWS * DINNER) return;
    int d = (int)(idx & (DINNER - 1));
    size_t bl = idx >> 11;
    int l = (int)(bl & (SEQ - 1));
    const float* p = xz + bl * (2 * DINNER) + d;
    float w0 = cw[d * 3 + 0], w1 = cw[d * 3 + 1], w2 = cw[d * 3 + 2];
    float acc = cb[d] + p[0] * w2;
    if (l >= 1) acc += p[-(2 * DINNER)] * w1;
    if (l >= 2) acc += p[-(ptrdiff_t)2 * (2 * DINNER)] * w0;
    float s = acc * (1.f / (1.f + __expf(-acc)));
    xp[idx] = s;
    bf16 h = __float2bfloat16(s);
    xph[idx] = h;
    xpl[idx] = __float2bfloat16(s - __bfloat162float(h));
}

// ---------------- Selective scan: 16 lanes per (b,d); gated output as bf16 hi/lo ----------------
__global__ __launch_bounds__(256)
void scan_kernel(const float* __restrict__ dt,
                 const float* __restrict__ dbc,
                 const float* __restrict__ xp,
                 const float* __restrict__ xz,
                 const float* __restrict__ A_log,
                 const float* __restrict__ Dp,
                 bf16* __restrict__ ygh, bf16* __restrict__ ygl,
                 float* __restrict__ hfinal)
{
    int t = blockIdx.x * blockDim.x + threadIdx.x;
    int lane = t & (DSTATE - 1);
    int group = t >> 4;
    if (group >= BATCH * DINNER) return;
    int b = group >> 11;
    int d = group & (DINNER - 1);

    float a = -__expf(A_log[d * DSTATE + lane]);
    float Dv = Dp[d];
    float h = 0.f;

    const float* dt_p = dt  + (size_t)b * SEQ * DINNER + d;
    const float* x_p  = xp  + (size_t)b * SEQ * DINNER + d;
    const float* z_p  = xz  + (size_t)b * SEQ * (2 * DINNER) + DINNER + d;
    const float* bc_p = dbc + (size_t)b * SEQ * DBCW + DTRANK + lane;
    size_t ybase = (size_t)b * SEQ * DINNER + d;

    for (int l = 0; l < SEQ; l++) {
        float dtv = dt_p[(size_t)l * DINNER];
        float xv  = x_p [(size_t)l * DINNER];
        float Bv  = bc_p[(size_t)l * DBCW];
        float Cv  = bc_p[(size_t)l * DBCW + DSTATE];
        h = __expf(dtv * a) * h + dtv * Bv * xv;
        float p = h * Cv;
        p += __shfl_xor_sync(0xffffffffu, p, 8);
        p += __shfl_xor_sync(0xffffffffu, p, 4);
        p += __shfl_xor_sync(0xffffffffu, p, 2);
        p += __shfl_xor_sync(0xffffffffu, p, 1);
        if (lane == 0) {
            float zv = z_p[(size_t)l * (2 * DINNER)];
            float sig = 1.f / (1.f + __expf(-zv));
            float yv = (p + xv * Dv) * (zv * sig);
            bf16 hb = __float2bfloat16(yv);
            ygh[ybase + (size_t)l * DINNER] = hb;
            ygl[ybase + (size_t)l * DINNER] = __float2bfloat16(yv - __bfloat162float(hb));
        }
    }
    hfinal[((size_t)b * DINNER + d) * DSTATE + lane] = h;
}

// ---------------- Launch ----------------
extern "C" void kernel_launch(void* const* d_in, const int* in_sizes, int n_in,
                              void* d_out, int out_size)
{
    const float* x        = (const float*)d_in[0];
    const float* in_w     = (const float*)d_in[1];
    const float* conv_w   = (const float*)d_in[2];
    const float* conv_b   = (const float*)d_in[3];
    const float* xproj_w  = (const float*)d_in[4];
    const float* dtproj_w = (const float*)d_in[5];
    const float* dtproj_b = (const float*)d_in[6];
    const float* A_log    = (const float*)d_in[7];
    const float* Dp       = (const float*)d_in[8];
    const float* out_w    = (const float*)d_in[9];
    const float* w1       = (const float*)d_in[10];
    const float* b1       = (const float*)d_in[11];
    const float* w2       = (const float*)d_in[12];
    const float* b2       = (const float*)d_in[13];
    float* out = (float*)d_out;

    float *xz, *xp, *dbc, *dt, *x2, *hstate;
    bf16 *xh, *xl, *inwh, *inwl, *xph, *xpl, *dbch, *dbcl, *dtwh, *dtwl, *xpwh, *xpwl;
    bf16 *owh, *owl, *w1h, *w1l, *w2h, *w2l, *ygh, *ygl, *x2h, *x2l, *hfh, *hfl;
    cudaGetSymbolAddress((void**)&xz,  g_xz);
    cudaGetSymbolAddress((void**)&xp,  g_xp);
    cudaGetSymbolAddress((void**)&dbc, g_dbc);
    cudaGetSymbolAddress((void**)&dt,  g_dt);
    cudaGetSymbolAddress((void**)&x2,  g_x2);
    cudaGetSymbolAddress((void**)&hstate, g_hstate);
    cudaGetSymbolAddress((void**)&xh,  g_xh);   cudaGetSymbolAddress((void**)&xl,  g_xl);
    cudaGetSymbolAddress((void**)&inwh,g_inwh); cudaGetSymbolAddress((void**)&inwl,g_inwl);
    cudaGetSymbolAddress((void**)&xph, g_xph);  cudaGetSymbolAddress((void**)&xpl, g_xpl);
    cudaGetSymbolAddress((void**)&dbch,g_dbch); cudaGetSymbolAddress((void**)&dbcl,g_dbcl);
    cudaGetSymbolAddress((void**)&dtwh,g_dtwh); cudaGetSymbolAddress((void**)&dtwl,g_dtwl);
    cudaGetSymbolAddress((void**)&xpwh,g_xpwh); cudaGetSymbolAddress((void**)&xpwl,g_xpwl);
    cudaGetSymbolAddress((void**)&owh, g_owh);  cudaGetSymbolAddress((void**)&owl, g_owl);
    cudaGetSymbolAddress((void**)&w1h, g_w1h);  cudaGetSymbolAddress((void**)&w1l, g_w1l);
    cudaGetSymbolAddress((void**)&w2h, g_w2h);  cudaGetSymbolAddress((void**)&w2l, g_w2l);
    cudaGetSymbolAddress((void**)&ygh, g_ygh);  cudaGetSymbolAddress((void**)&ygl, g_ygl);
    cudaGetSymbolAddress((void**)&x2h, g_x2h);  cudaGetSymbolAddress((void**)&x2l, g_x2l);
    cudaGetSymbolAddress((void**)&hfh, g_hfh);  cudaGetSymbolAddress((void**)&hfl, g_hfl);

    cudaFuncSetAttribute(gemm_tc, cudaFuncAttributeMaxDynamicSharedMemorySize, GEMM_SMEM);

    const int xout_elems = MROWS * DMODEL;
    const int h_elems    = BATCH * DINNER * DSTATE;
    float* hdst = (out_size >= xout_elems + h_elems) ? (out + xout_elems) : hstate;

    auto grid = [](int m, int n) { return dim3((unsigned)((n + TCBN - 1) / TCBN),
                                               (unsigned)((m + TCBM - 1) / TCBM)); };
    auto sgrid = [](int n) { return (unsigned)((n + 255) / 256); };

    // 1: all weight/input splits in one launch
    split_all<<<(F4_B6 + 255) / 256, 256>>>(x, xh, xl, in_w, inwh, inwl,
                                            xproj_w, xpwh, xpwl, dtproj_w, dtwh, dtwl,
                                            out_w, owh, owl, w1, w1h, w1l, w2, w2h, w2l);

    // 2: G1: xz = x @ in_proj_w^T   (4096 x 4096, K=1024)
    gemm_tc<<<grid(MROWS, 2 * DINNER), 256, GEMM_SMEM>>>(MROWS, 2 * DINNER, DMODEL,
        xh, xl, DMODEL, inwh, inwl, DMODEL, xz, 2 * DINNER, nullptr, nullptr, 0, nullptr, nullptr, 0);

    // 3: conv + SiLU -> xp (fp32 + hi/lo)
    conv_silu_kernel<<<sgrid(MROWS * DINNER), 256>>>(xz, conv_w, conv_b, xp, xph, xpl);

    // 4: G2: dbc = xp @ x_proj_w^T  (4096 x 96, K=2048); epilogue also emits hi/lo split
    gemm_tc<<<grid(MROWS, DBCW), 256, GEMM_SMEM>>>(MROWS, DBCW, DINNER,
        xph, xpl, DINNER, xpwh, xpwl, DINNER, dbc, DBCW, dbch, dbcl, 0, nullptr, nullptr, 0);

    // 5: G3: dt = softplus(dbc[:, :64] @ dt_proj_w^T + b)  (4096 x 2048, K=64)
    gemm_tc<<<grid(MROWS, DINNER), 256, GEMM_SMEM>>>(MROWS, DINNER, DTRANK,
        dbch, dbcl, DBCW, dtwh, dtwl, DTRANK, dt, DINNER, nullptr, nullptr, 1, dtproj_b, nullptr, 0);

    // 6: SSM scan + D-skip + SiLU(z) gate -> yg (hi/lo), h_final
    scan_kernel<<<(BATCH * DINNER * DSTATE) / 256, 256>>>(dt, dbc, xp, xz, A_log, Dp, ygh, ygl, hdst);

    // 7: G4: x2 = x + yg @ out_proj_w^T   (4096 x 1024, K=2048)  (fp32 + hi/lo)
    gemm_tc<<<grid(MROWS, DMODEL), 256, GEMM_SMEM>>>(MROWS, DMODEL, DINNER,
        ygh, ygl, DINNER, owh, owl, DINNER, x2, DMODEL, x2h, x2l, 2, nullptr, x, DMODEL);

    // 8: G5: hf = gelu(x2 @ w1^T + b1)    (4096 x 4096, K=1024)  (hi/lo only)
    gemm_tc<<<grid(MROWS, DFFN), 256, GEMM_SMEM>>>(MROWS, DFFN, DMODEL,
        x2h, x2l, DMODEL, w1h, w1l, DMODEL, nullptr, DFFN, hfh, hfl, 3, b1, nullptr, 0);

    // 9: G6: out = x2 + hf @ w2^T + b2    (4096 x 1024, K=4096)
    gemm_tc<<<grid(MROWS, DMODEL), 256, GEMM_SMEM>>>(MROWS, DMODEL, DFFN,
        hfh, hfl, DFFN, w2h, w2l, DFFN, out, DMODEL, nullptr, nullptr, 4, b2, x2, DMODEL);
}

// round 7
// speedup vs baseline: 1.6085x; 1.0212x over previous
#include <cuda_runtime.h>
#include <cuda_bf16.h>
#include <math.h>
#include <stdint.h>

// ---------------- Problem constants ----------------
#define BATCH   2
#define SEQ     2048
#define DMODEL  1024
#define DINNER  2048
#define DSTATE  16
#define DTRANK  64
#define DFFN    4096
#define MROWS   (BATCH*SEQ)          // 4096
#define DBCW    (DTRANK + 2*DSTATE)  // 96

typedef __nv_bfloat16 bf16;

// ---------------- Scratch (static device globals; no allocation) ----------------
__device__ float g_xz [(size_t)MROWS * (2*DINNER)];  // 4096 x 4096 (xp | z)
__device__ float g_xp [(size_t)MROWS * DINNER];
__device__ float g_dbc[(size_t)MROWS * DBCW];
__device__ float g_dt [(size_t)MROWS * DINNER];
__device__ float g_x2 [(size_t)MROWS * DMODEL];
__device__ float g_hstate[(size_t)BATCH * DINNER * DSTATE];

__device__ bf16 g_xh  [(size_t)MROWS * DMODEL],      g_xl  [(size_t)MROWS * DMODEL];
__device__ bf16 g_inwh[(size_t)(2*DINNER) * DMODEL], g_inwl[(size_t)(2*DINNER) * DMODEL];
__device__ bf16 g_xph [(size_t)MROWS * DINNER],      g_xpl [(size_t)MROWS * DINNER];
__device__ bf16 g_dbch[(size_t)MROWS * DBCW],        g_dbcl[(size_t)MROWS * DBCW];
__device__ bf16 g_dtwh[(size_t)DINNER * DTRANK],     g_dtwl[(size_t)DINNER * DTRANK];
__device__ bf16 g_xpwh[(size_t)DBCW * DINNER],       g_xpwl[(size_t)DBCW * DINNER];
__device__ bf16 g_owh [(size_t)DMODEL * DINNER],     g_owl [(size_t)DMODEL * DINNER];
__device__ bf16 g_w1h [(size_t)DFFN * DMODEL],       g_w1l [(size_t)DFFN * DMODEL];
__device__ bf16 g_w2h [(size_t)DMODEL * DFFN],       g_w2l [(size_t)DMODEL * DFFN];
__device__ bf16 g_ygh [(size_t)MROWS * DINNER],      g_ygl [(size_t)MROWS * DINNER];
__device__ bf16 g_x2h [(size_t)MROWS * DMODEL],      g_x2l [(size_t)MROWS * DMODEL];
__device__ bf16 g_hfh [(size_t)MROWS * DFFN],        g_hfl [(size_t)MROWS * DFFN];

// ---------------- low-level helpers (sm_80+ baseline; no 'a'-gated instrs) ----------------
__device__ __forceinline__ uint32_t smem_u32(const void* p) {
    uint32_t a;
    asm("{ .reg .u64 t; cvta.to.shared.u64 t, %1; cvt.u32.u64 %0, t; }" : "=r"(a) : "l"(p));
    return a;
}
__device__ __forceinline__ void cp_async16(uint32_t dst, const void* src, uint32_t srcBytes) {
    asm volatile("cp.async.cg.shared.global [%0], [%1], 16, %2;"
                 :: "r"(dst), "l"(src), "r"(srcBytes));
}
__device__ __forceinline__ void cp_commit() { asm volatile("cp.async.commit_group;"); }
__device__ __forceinline__ void cp_wait1()  { asm volatile("cp.async.wait_group 1;"); }

__device__ __forceinline__ void ldmatrix_x4(uint32_t* r, uint32_t addr) {
    asm volatile("ldmatrix.sync.aligned.m8n8.x4.shared.b16 {%0,%1,%2,%3}, [%4];"
                 : "=r"(r[0]), "=r"(r[1]), "=r"(r[2]), "=r"(r[3]) : "r"(addr));
}
__device__ __forceinline__ void mma16816(float* d, const uint32_t* a, const uint32_t* b) {
    asm volatile("mma.sync.aligned.m16n8k16.row.col.f32.bf16.bf16.f32 "
                 "{%0,%1,%2,%3}, {%4,%5,%6,%7}, {%8,%9}, {%0,%1,%2,%3};"
                 : "+f"(d[0]), "+f"(d[1]), "+f"(d[2]), "+f"(d[3])
                 : "r"(a[0]), "r"(a[1]), "r"(a[2]), "r"(a[3]), "r"(b[0]), "r"(b[1]));
}

// ---------------- fused fp32 -> bf16 hi/lo split over all weight/input tensors ----------------
#define F4_X    1048576u
#define F4_INW  1048576u
#define F4_XPW    49152u
#define F4_DTW    32768u
#define F4_OW    524288u
#define F4_W1   1048576u
#define F4_W2   1048576u
#define F4_B0   F4_X
#define F4_B1   (F4_B0 + F4_INW)
#define F4_B2   (F4_B1 + F4_XPW)
#define F4_B3   (F4_B2 + F4_DTW)
#define F4_B4   (F4_B3 + F4_OW)
#define F4_B5   (F4_B4 + F4_W1)
#define F4_B6   (F4_B5 + F4_W2)

struct BF4 { bf16 v[4]; };

__global__ __launch_bounds__(256)
void split_all(const float* __restrict__ x,    bf16* __restrict__ xh,   bf16* __restrict__ xl,
               const float* __restrict__ inw,  bf16* __restrict__ inwh, bf16* __restrict__ inwl,
               const float* __restrict__ xpw,  bf16* __restrict__ xpwh, bf16* __restrict__ xpwl,
               const float* __restrict__ dtw,  bf16* __restrict__ dtwh, bf16* __restrict__ dtwl,
               const float* __restrict__ ow,   bf16* __restrict__ owh,  bf16* __restrict__ owl,
               const float* __restrict__ w1,   bf16* __restrict__ w1h,  bf16* __restrict__ w1l,
               const float* __restrict__ w2,   bf16* __restrict__ w2h,  bf16* __restrict__ w2l)
{
    uint32_t i = blockIdx.x * blockDim.x + threadIdx.x;
    if (i >= F4_B6) return;
    const float* src; bf16 *hi, *lo; uint32_t off;
    if      (i < F4_B0) { src = x;   hi = xh;   lo = xl;   off = i; }
    else if (i < F4_B1) { src = inw; hi = inwh; lo = inwl; off = i - F4_B0; }
    else if (i < F4_B2) { src = xpw; hi = xpwh; lo = xpwl; off = i - F4_B1; }
    else if (i < F4_B3) { src = dtw; hi = dtwh; lo = dtwl; off = i - F4_B2; }
    else if (i < F4_B4) { src = ow;  hi = owh;  lo = owl;  off = i - F4_B3; }
    else if (i < F4_B5) { src = w1;  hi = w1h;  lo = w1l;  off = i - F4_B4; }
    else                { src = w2;  hi = w2h;  lo = w2l;  off = i - F4_B5; }
    float4 v = reinterpret_cast<const float4*>(src)[off];
    BF4 h, l;
    float a[4] = {v.x, v.y, v.z, v.w};
#pragma unroll
    for (int k = 0; k < 4; k++) {
        bf16 hb = __float2bfloat16(a[k]);
        h.v[k] = hb;
        l.v[k] = __float2bfloat16(a[k] - __bfloat162float(hb));
    }
    reinterpret_cast<BF4*>(hi)[off] = h;
    reinterpret_cast<BF4*>(lo)[off] = l;
}

// ---------------- split-bf16 mma.sync GEMM: C[M,N] = A[M,K] * B[N,K]^T ----------------
// 128x64 tile, 4 warps, 3-stage cp.async pipeline, 2 CTAs/SM.
// epi: 0=plain fp32; 1=softplus(v+bias); 2=v+res; 3=gelu(v+bias); 4=v+bias+res
#define TCBM 128
#define TCBN 64
#define TCBK 32
#define ROWSTRIDE 40                     // bf16 elems per smem row (80 bytes)
#define ATILE_B  (128 * ROWSTRIDE * 2)   // 10240 bytes (128 rows)
#define BTILE_B  (64 * ROWSTRIDE * 2)    // 5120 bytes (64 rows)
#define STAGE_B  (2 * ATILE_B + 2 * BTILE_B)  // Ah, Al, Bh, Bl = 30720
#define OFF_AH 0
#define OFF_AL ATILE_B
#define OFF_BH (2 * ATILE_B)
#define OFF_BL (2 * ATILE_B + BTILE_B)
#define NSTAGE   3
#define GEMM_SMEM (NSTAGE * STAGE_B)     // 92160

__global__ __launch_bounds__(128, 2)
void gemm_tc(int M, int N, int K,
             const bf16* __restrict__ Ahi, const bf16* __restrict__ Alo, int lda,
             const bf16* __restrict__ Bhi, const bf16* __restrict__ Blo, int ldb,
             float* __restrict__ Cf, int ldc,
             bf16* __restrict__ Chi, bf16* __restrict__ Clo,
             int epi, const float* __restrict__ bias,
             const float* __restrict__ res, int ldres)
{
    extern __shared__ char smem[];
    const uint32_t sbase = smem_u32(smem);
    const int tid = threadIdx.x;
    const int wid = tid >> 5;
    const int lane = tid & 31;
    const int wm = (wid & 1) * 64;       // warp m offset (2 warps in m)
    const int wn = (wid >> 1) * 32;      // warp n offset (2 warps in n)

    const int bm = blockIdx.y * TCBM;
    const int bn = blockIdx.x * TCBN;
    const int nk = K / TCBK;

    float acc[4][4][4];
#pragma unroll
    for (int i = 0; i < 4; i++)
#pragma unroll
        for (int j = 0; j < 4; j++)
#pragma unroll
            for (int r = 0; r < 4; r++) acc[i][j][r] = 0.f;

    // stage holds 1536 uint4: [0,512) Ah, [512,1024) Al, [1024,1280) Bh, [1280,1536) Bl
    auto prefetch = [&](int t, int stg) {
        const int k0 = t * TCBK;
        const uint32_t stage = sbase + (uint32_t)stg * STAGE_B;
#pragma unroll
        for (int q = 0; q < 12; q++) {
            int idx = q * 128 + tid;     // 0..1535
            int ch  = idx & 3;
            const bf16* g; int grow, ld, lim; uint32_t moff; int r;
            if (idx < 1024) {
                r = (idx >> 2) & 127;
                if (idx < 512) { g = Ahi; moff = OFF_AH; }
                else           { g = Alo; moff = OFF_AL; }
                grow = bm + r; ld = lda; lim = M;
            } else {
                r = (idx >> 2) & 63;
                if (idx < 1280) { g = Bhi; moff = OFF_BH; }
                else            { g = Blo; moff = OFF_BL; }
                grow = bn + r; ld = ldb; lim = N;
            }
            uint32_t ok = (grow < lim) ? 16u : 0u;
            if (grow >= lim) grow = 0;   // keep address valid
            uint32_t dst = stage + moff + (uint32_t)r * (ROWSTRIDE * 2) + (uint32_t)ch * 16;
            cp_async16(dst, g + (size_t)grow * ld + k0 + ch * 8, ok);
        }
    };

    prefetch(0, 0);
    cp_commit();
    if (nk > 1) prefetch(1, 1);
    cp_commit();

    int cstg = 0, pstg = 2;
    for (int t = 0; t < nk; t++) {
        cp_wait1();                         // stage t resident
        __syncthreads();                    // all warps done with stage pstg's last use
        if (t + 2 < nk) prefetch(t + 2, pstg);
        cp_commit();

        const uint32_t stage = sbase + (uint32_t)cstg * STAGE_B;
        const uint32_t sAh = stage + OFF_AH, sAl = stage + OFF_AL;
        const uint32_t sBh = stage + OFF_BH, sBl = stage + OFF_BL;

        // B fragments for the whole k32 iter: x4 = four k8 chunks per n8 block
        uint32_t bh4[4][4], bl4[4][4];
#pragma unroll
        for (int ni = 0; ni < 4; ni++) {
            uint32_t boff = (uint32_t)(wn + ni * 8 + (lane & 7)) * (ROWSTRIDE * 2) + (uint32_t)(lane >> 3) * 16;
            ldmatrix_x4(bh4[ni], sBh + boff);
            ldmatrix_x4(bl4[ni], sBl + boff);
        }

#pragma unroll
        for (int kh = 0; kh < 2; kh++) {   // two k16 steps
            const uint32_t aoff = (uint32_t)(wm + (lane & 15)) * (ROWSTRIDE * 2) + (uint32_t)(kh * 16 + (lane >> 4) * 8) * 2;
            uint32_t ah[4][4], al[4][4];
#pragma unroll
            for (int mi = 0; mi < 4; mi++) {
                ldmatrix_x4(ah[mi], sAh + aoff + (uint32_t)(mi * 16) * (ROWSTRIDE * 2));
                ldmatrix_x4(al[mi], sAl + aoff + (uint32_t)(mi * 16) * (ROWSTRIDE * 2));
            }
#pragma unroll
            for (int mi = 0; mi < 4; mi++)
#pragma unroll
                for (int ni = 0; ni < 4; ni++) {
                    mma16816(acc[mi][ni], ah[mi], &bh4[ni][kh * 2]);
                    mma16816(acc[mi][ni], al[mi], &bh4[ni][kh * 2]);
                    mma16816(acc[mi][ni], ah[mi], &bl4[ni][kh * 2]);
                }
        }
        if (++cstg == NSTAGE) cstg = 0;
        if (++pstg == NSTAGE) pstg = 0;
    }

    // ---- epilogue straight from registers ----
#pragma unroll
    for (int mi = 0; mi < 4; mi++) {
#pragma unroll
        for (int ni = 0; ni < 4; ni++) {
#pragma unroll
            for (int ri = 0; ri < 4; ri++) {
                int row = bm + wm + mi * 16 + (lane >> 2) + (ri >> 1) * 8;
                int col = bn + wn + ni * 8 + (lane & 3) * 2 + (ri & 1);
                if (row >= M || col >= N) continue;
                float v = acc[mi][ni][ri];
                if (epi == 1) {
                    v += bias[col];
                    v = (v >= 0.f) ? (v + log1pf(expf(-v))) : log1pf(expf(v));
                } else if (epi == 2) {
                    v += res[(size_t)row * ldres + col];
                } else if (epi == 3) {
                    v += bias[col];
                    v = 0.5f * v * (1.f + erff(v * 0.70710678118654752440f));
                } else if (epi == 4) {
                    v += bias[col] + res[(size_t)row * ldres + col];
                }
                if (Cf) Cf[(size_t)row * ldc + col] = v;
                if (Chi) {
                    bf16 h = __float2bfloat16(v);
                    Chi[(size_t)row * ldc + col] = h;
                    Clo[(size_t)row * ldc + col] = __float2bfloat16(v - __bfloat162float(h));
                }
            }
        }
    }
}

// ---------------- Depthwise causal conv (K=3) + bias + SiLU (+ bf16 split out) ----------------
__global__ __launch_bounds__(256)
void conv_silu_kernel(const float* __restrict__ xz,
                      const float* __restrict__ cw,
                      const float* __restrict__ cb,
                      float* __restrict__ xp,
                      bf16* __restrict__ xph, bf16* __restrict__ xpl)
{
    size_t idx = (size_t)blockIdx.x * blockDim.x + threadIdx.x;
    if (idx >= (size_t)MROWS * DINNER) return;
    int d = (int)(idx & (DINNER - 1));
    size_t bl = idx >> 11;
    int l = (int)(bl & (SEQ - 1));
    const float* p = xz + bl * (2 * DINNER) + d;
    float w0 = cw[d * 3 + 0], w1 = cw[d * 3 + 1], w2 = cw[d * 3 + 2];
    float acc = cb[d] + p[0] * w2;
    if (l >= 1) acc += p[-(2 * DINNER)] * w1;
    if (l >= 2) acc += p[-(ptrdiff_t)2 * (2 * DINNER)] * w0;
    float s = acc * (1.f / (1.f + __expf(-acc)));
    xp[idx] = s;
    bf16 h = __float2bfloat16(s);
    xph[idx] = h;
    xpl[idx] = __float2bfloat16(s - __bfloat162float(h));
}

// ---------------- Selective scan: 16 lanes per (b,d); gated output as bf16 hi/lo ----------------
__global__ __launch_bounds__(256)
void scan_kernel(const float* __restrict__ dt,
                 const float* __restrict__ dbc,
                 const float* __restrict__ xp,
                 const float* __restrict__ xz,
                 const float* __restrict__ A_log,
                 const float* __restrict__ Dp,
                 bf16* __restrict__ ygh, bf16* __restrict__ ygl,
                 float* __restrict__ hfinal)
{
    int t = blockIdx.x * blockDim.x + threadIdx.x;
    int lane = t & (DSTATE - 1);
    int group = t >> 4;
    if (group >= BATCH * DINNER) return;
    int b = group >> 11;
    int d = group & (DINNER - 1);

    float a = -__expf(A_log[d * DSTATE + lane]);
    float Dv = Dp[d];
    float h = 0.f;

    const float* dt_p = dt  + (size_t)b * SEQ * DINNER + d;
    const float* x_p  = xp  + (size_t)b * SEQ * DINNER + d;
    const float* z_p  = xz  + (size_t)b * SEQ * (2 * DINNER) + DINNER + d;
    const float* bc_p = dbc + (size_t)b * SEQ * DBCW + DTRANK + lane;
    size_t ybase = (size_t)b * SEQ * DINNER + d;

    for (int l = 0; l < SEQ; l++) {
        float dtv = dt_p[(size_t)l * DINNER];
        float xv  = x_p [(size_t)l * DINNER];
        float Bv  = bc_p[(size_t)l * DBCW];
        float Cv  = bc_p[(size_t)l * DBCW + DSTATE];
        h = __expf(dtv * a) * h + dtv * Bv * xv;
        float p = h * Cv;
        p += __shfl_xor_sync(0xffffffffu, p, 8);
        p += __shfl_xor_sync(0xffffffffu, p, 4);
        p += __shfl_xor_sync(0xffffffffu, p, 2);
        p += __shfl_xor_sync(0xffffffffu, p, 1);
        if (lane == 0) {
            float zv = z_p[(size_t)l * (2 * DINNER)];
            float sig = 1.f / (1.f + __expf(-zv));
            float yv = (p + xv * Dv) * (zv * sig);
            bf16 hb = __float2bfloat16(yv);
            ygh[ybase + (size_t)l * DINNER] = hb;
            ygl[ybase + (size_t)l * DINNER] = __float2bfloat16(yv - __bfloat162float(hb));
        }
    }
    hfinal[((size_t)b * DINNER + d) * DSTATE + lane] = h;
}

// ---------------- Launch ----------------
extern "C" void kernel_launch(void* const* d_in, const int* in_sizes, int n_in,
                              void* d_out, int out_size)
{
    const float* x        = (const float*)d_in[0];
    const float* in_w     = (const float*)d_in[1];
    const float* conv_w   = (const float*)d_in[2];
    const float* conv_b   = (const float*)d_in[3];
    const float* xproj_w  = (const float*)d_in[4];
    const float* dtproj_w = (const float*)d_in[5];
    const float* dtproj_b = (const float*)d_in[6];
    const float* A_log    = (const float*)d_in[7];
    const float* Dp       = (const float*)d_in[8];
    const float* out_w    = (const float*)d_in[9];
    const float* w1       = (const float*)d_in[10];
    const float* b1       = (const float*)d_in[11];
    const float* w2       = (const float*)d_in[12];
    const float* b2       = (const float*)d_in[13];
    float* out = (float*)d_out;

    float *xz, *xp, *dbc, *dt, *x2, *hstate;
    bf16 *xh, *xl, *inwh, *inwl, *xph, *xpl, *dbch, *dbcl, *dtwh, *dtwl, *xpwh, *xpwl;
    bf16 *owh, *owl, *w1h, *w1l, *w2h, *w2l, *ygh, *ygl, *x2h, *x2l, *hfh, *hfl;
    cudaGetSymbolAddress((void**)&xz,  g_xz);
    cudaGetSymbolAddress((void**)&xp,  g_xp);
    cudaGetSymbolAddress((void**)&dbc, g_dbc);
    cudaGetSymbolAddress((void**)&dt,  g_dt);
    cudaGetSymbolAddress((void**)&x2,  g_x2);
    cudaGetSymbolAddress((void**)&hstate, g_hstate);
    cudaGetSymbolAddress((void**)&xh,  g_xh);   cudaGetSymbolAddress((void**)&xl,  g_xl);
    cudaGetSymbolAddress((void**)&inwh,g_inwh); cudaGetSymbolAddress((void**)&inwl,g_inwl);
    cudaGetSymbolAddress((void**)&xph, g_xph);  cudaGetSymbolAddress((void**)&xpl, g_xpl);
    cudaGetSymbolAddress((void**)&dbch,g_dbch); cudaGetSymbolAddress((void**)&dbcl,g_dbcl);
    cudaGetSymbolAddress((void**)&dtwh,g_dtwh); cudaGetSymbolAddress((void**)&dtwl,g_dtwl);
    cudaGetSymbolAddress((void**)&xpwh,g_xpwh); cudaGetSymbolAddress((void**)&xpwl,g_xpwl);
    cudaGetSymbolAddress((void**)&owh, g_owh);  cudaGetSymbolAddress((void**)&owl, g_owl);
    cudaGetSymbolAddress((void**)&w1h, g_w1h);  cudaGetSymbolAddress((void**)&w1l, g_w1l);
    cudaGetSymbolAddress((void**)&w2h, g_w2h);  cudaGetSymbolAddress((void**)&w2l, g_w2l);
    cudaGetSymbolAddress((void**)&ygh, g_ygh);  cudaGetSymbolAddress((void**)&ygl, g_ygl);
    cudaGetSymbolAddress((void**)&x2h, g_x2h);  cudaGetSymbolAddress((void**)&x2l, g_x2l);
    cudaGetSymbolAddress((void**)&hfh, g_hfh);  cudaGetSymbolAddress((void**)&hfl, g_hfl);

    cudaFuncSetAttribute(gemm_tc, cudaFuncAttributeMaxDynamicSharedMemorySize, GEMM_SMEM);

    const int xout_elems = MROWS * DMODEL;
    const int h_elems    = BATCH * DINNER * DSTATE;
    float* hdst = (out_size >= xout_elems + h_elems) ? (out + xout_elems) : hstate;

    auto grid = [](int m, int n) { return dim3((unsigned)((n + TCBN - 1) / TCBN),
                                               (unsigned)((m + TCBM - 1) / TCBM)); };
    auto sgrid = [](int n) { return (unsigned)((n + 255) / 256); };

    // 1: all weight/input splits in one launch
    split_all<<<(F4_B6 + 255) / 256, 256>>>(x, xh, xl, in_w, inwh, inwl,
                                            xproj_w, xpwh, xpwl, dtproj_w, dtwh, dtwl,
                                            out_w, owh, owl, w1, w1h, w1l, w2, w2h, w2l);

    // 2: G1: xz = x @ in_proj_w^T   (4096 x 4096, K=1024)
    gemm_tc<<<grid(MROWS, 2 * DINNER), 128, GEMM_SMEM>>>(MROWS, 2 * DINNER, DMODEL,
        xh, xl, DMODEL, inwh, inwl, DMODEL, xz, 2 * DINNER, nullptr, nullptr, 0, nullptr, nullptr, 0);

    // 3: conv + SiLU -> xp (fp32 + hi/lo)
    conv_silu_kernel<<<sgrid(MROWS * DINNER), 256>>>(xz, conv_w, conv_b, xp, xph, xpl);

    // 4: G2: dbc = xp @ x_proj_w^T  (4096 x 96, K=2048); epilogue also emits hi/lo split
    gemm_tc<<<grid(MROWS, DBCW), 128, GEMM_SMEM>>>(MROWS, DBCW, DINNER,
        xph, xpl, DINNER, xpwh, xpwl, DINNER, dbc, DBCW, dbch, dbcl, 0, nullptr, nullptr, 0);

    // 5: G3: dt = softplus(dbc[:, :64] @ dt_proj_w^T + b)  (4096 x 2048, K=64)
    gemm_tc<<<grid(MROWS, DINNER), 128, GEMM_SMEM>>>(MROWS, DINNER, DTRANK,
        dbch, dbcl, DBCW, dtwh, dtwl, DTRANK, dt, DINNER, nullptr, nullptr, 1, dtproj_b, nullptr, 0);

    // 6: SSM scan + D-skip + SiLU(z) gate -> yg (hi/lo), h_final
    scan_kernel<<<(BATCH * DINNER * DSTATE) / 256, 256>>>(dt, dbc, xp, xz, A_log, Dp, ygh, ygl, hdst);

    // 7: G4: x2 = x + yg @ out_proj_w^T   (4096 x 1024, K=2048)  (fp32 + hi/lo)
    gemm_tc<<<grid(MROWS, DMODEL), 128, GEMM_SMEM>>>(MROWS, DMODEL, DINNER,
        ygh, ygl, DINNER, owh, owl, DINNER, x2, DMODEL, x2h, x2l, 2, nullptr, x, DMODEL);

    // 8: G5: hf = gelu(x2 @ w1^T + b1)    (4096 x 4096, K=1024)  (hi/lo only)
    gemm_tc<<<grid(MROWS, DFFN), 128, GEMM_SMEM>>>(MROWS, DFFN, DMODEL,
        x2h, x2l, DMODEL, w1h, w1l, DMODEL, nullptr, DFFN, hfh, hfl, 3, b1, nullptr, 0);

    // 9: G6: out = x2 + hf @ w2^T + b2    (4096 x 1024, K=4096)
    gemm_tc<<<grid(MROWS, DMODEL), 128, GEMM_SMEM>>>(MROWS, DMODEL, DFFN,
        hfh, hfl, DFFN, w2h, w2l, DFFN, out, DMODEL, nullptr, nullptr, 4, b2, x2, DMODEL);
}